// round 15
// baseline (speedup 1.0000x reference)
#include <cuda_runtime.h>
#include <cuda_fp16.h>
#include <cstdint>

// ---------------------------------------------------------------------------
// PatchNCELoss B=8192 D=128 T=0.07 via mma.sync m16n8k32 s8 (IMMA, s32 acc).
// loss[b] = 1/T + log(sum_k exp((S[b,k]-1)/T)) - pos[b]/T
// Normalized rows quantized to s8*127; logits = acc/127^2. Epilogue converts
// s32 via magic-bias (IADD+FFMA, no I2F) then ex2. pos/T exact fp32 from prep.
// R15 = R14 pipeline (prep w/ aggregated atomics, in-gemm A permute, lg2
// finalize) with the GEMM core on int8.
// ---------------------------------------------------------------------------

#define BN  8192
#define BN2 8320              // 65 * 128
#define DD  128
#define KS  4                 // key splits
#define NC  16                // 128-key chunks per CTA (8192/128/KS)
#define GRID_X 65

#define INV_T    14.285714285714286f
#define SCALE_L2 20.609929155556620f   /* log2(e)/T */
#define LN2      0.69314718055994531f
#define KQ   ((float)(20.609929155556620 / 16129.0))
#define CEPI ((float)(-20.609929155556620 - 12582912.0 * (20.609929155556620 / 16129.0)))
#define MAGIC_I 0x4B400000

static __device__ uint32_t g_At8[BN2 * 32];   // row-major s8 A (by slot), x127
static __device__ uint32_t g_Bv8[BN * 32];    // fragment-permuted s8 v_n keys
static __device__ uint32_t g_Bi8[BN * 32];    // fragment-permuted s8 i_n keys
static __device__ float    g_posT[BN2];
static __device__ int      g_orig[BN2];
static __device__ int      g_cnt[2];
static __device__ int      g_c0s;
static __device__ float    g_partial[KS * BN2];

// smem: A 16KB | B0 16KB | B1 16KB (B1 doubles as A staging in prologue)
#define SMEM_TOT 49152

// ---------------------------------------------------------------------------
__device__ __forceinline__ float ex2f(float x) {
    float r; asm("ex2.approx.f32 %0,%1;" : "=f"(r) : "f"(x)); return r;
}
__device__ __forceinline__ float lg2f(float x) {
    float r; asm("lg2.approx.f32 %0,%1;" : "=f"(r) : "f"(x)); return r;
}
__device__ __forceinline__ uint32_t s2u(const void* p) {
    uint32_t a;
    asm("{ .reg .u64 t; cvta.to.shared.u64 t, %1; cvt.u32.u64 %0, t; }"
        : "=r"(a) : "l"(p));
    return a;
}
#define CPA16(dst, src) \
    asm volatile("cp.async.cg.shared.global [%0], [%1], 16;" :: "r"(dst), "l"(src))
#define CP_COMMIT() asm volatile("cp.async.commit_group;" ::: "memory")
#define CP_WAIT1()  asm volatile("cp.async.wait_group 1;" ::: "memory")
#define CP_WAIT0()  asm volatile("cp.async.wait_group 0;" ::: "memory")

#define LDS128(r, a) \
    asm volatile("ld.shared.v4.b32 {%0,%1,%2,%3}, [%4];" \
        : "=r"((r)[0]), "=r"((r)[1]), "=r"((r)[2]), "=r"((r)[3]) : "r"(a))
#define LDS64(r, a) \
    asm volatile("ld.shared.v2.b32 {%0,%1}, [%2];" \
        : "=r"((r)[0]), "=r"((r)[1]) : "r"(a))

__device__ __forceinline__ void imma16832(int* c, const uint32_t* a,
                                          const uint32_t* b) {
    asm volatile(
        "mma.sync.aligned.m16n8k32.row.col.s32.s8.s8.s32 "
        "{%0,%1,%2,%3}, {%4,%5,%6,%7}, {%8,%9}, {%0,%1,%2,%3};"
        : "+r"(c[0]), "+r"(c[1]), "+r"(c[2]), "+r"(c[3])
        : "r"(a[0]), "r"(a[1]), "r"(a[2]), "r"(a[3]), "r"(b[0]), "r"(b[1]));
}

__device__ __forceinline__ uint32_t pack_s8(float x0, float x1, float x2,
                                            float x3, float sc) {
    int v0 = __float2int_rn(x0 * sc), v1 = __float2int_rn(x1 * sc);
    int v2 = __float2int_rn(x2 * sc), v3 = __float2int_rn(x3 * sc);
    return (uint32_t)(v0 & 255) | ((uint32_t)(v1 & 255) << 8) |
           ((uint32_t)(v2 & 255) << 16) | ((uint32_t)v3 << 24);
}

// ---------------------------------------------------------------------------
// prep: 512 threads, 2 rows per warp (32 rows/block, 256 blocks), MLP-8,
// block-aggregated compaction (2 atomics/block),
// B fragment-perm (s8, m16n8k32) staged in smem -> coalesced writes,
// A row-major s8 by slot (4B/lane coalesced).
__global__ __launch_bounds__(512) void prep_kernel(
        const float* __restrict__ fv, const float* __restrict__ fi,
        const float* __restrict__ v,  const float* __restrict__ vi) {
    __shared__ __align__(16) uint32_t bvs[1024];  // 4 nb blocks x 256 uint32
    __shared__ __align__(16) uint32_t bis[1024];
    __shared__ int sh_use[32];
    __shared__ int sh_slot[32];

    int tid  = threadIdx.x;
    int w    = tid >> 5;
    int lane = tid & 31;
    int b0   = blockIdx.x * 32 + w * 2;

    float4 Lfv[2], Lfi[2], Lv[2], Li[2];
#pragma unroll
    for (int rr = 0; rr < 2; ++rr) {
        int b = b0 + rr;
        Lfv[rr] = __ldg((const float4*)(fv + b * DD + lane * 4));
        Lfi[rr] = __ldg((const float4*)(fi + b * DD + lane * 4));
        Lv[rr]  = __ldg((const float4*)(v  + b * DD + lane * 4));
        Li[rr]  = __ldg((const float4*)(vi + b * DD + lane * 4));
    }

    float s[12];
#pragma unroll
    for (int rr = 0; rr < 2; ++rr) {
        float4 a = Lfv[rr], c = Lfi[rr], d = Lv[rr], e = Li[rr];
        s[rr*6+0] = a.x*a.x + a.y*a.y + a.z*a.z + a.w*a.w;
        s[rr*6+1] = c.x*c.x + c.y*c.y + c.z*c.z + c.w*c.w;
        s[rr*6+2] = d.x*d.x + d.y*d.y + d.z*d.z + d.w*d.w;
        s[rr*6+3] = e.x*e.x + e.y*e.y + e.z*e.z + e.w*e.w;
        s[rr*6+4] = a.x*d.x + a.y*d.y + a.z*d.z + a.w*d.w;
        s[rr*6+5] = c.x*e.x + c.y*e.y + c.z*e.z + c.w*e.w;
    }
#pragma unroll
    for (int off = 16; off; off >>= 1)
#pragma unroll
        for (int k = 0; k < 12; ++k)
            s[k] += __shfl_xor_sync(0xffffffffu, s[k], off);

    float inv_fv[2], inv_fi[2], inv_v[2], inv_i[2], posb[2];
    bool use_v[2];
#pragma unroll
    for (int rr = 0; rr < 2; ++rr) {
        inv_fv[rr] = 1.f / fmaxf(sqrtf(s[rr*6+0]), 1e-12f);
        inv_fi[rr] = 1.f / fmaxf(sqrtf(s[rr*6+1]), 1e-12f);
        inv_v[rr]  = 1.f / fmaxf(sqrtf(s[rr*6+2]), 1e-12f);
        inv_i[rr]  = 1.f / fmaxf(sqrtf(s[rr*6+3]), 1e-12f);
        float pos_v = s[rr*6+4] * inv_fv[rr] * inv_v[rr];
        float pos_i = s[rr*6+5] * inv_fi[rr] * inv_i[rr];
        use_v[rr] = (pos_v >= pos_i);
        posb[rr] = use_v[rr] ? pos_v : pos_i;
        if (lane == 0) sh_use[w*2+rr] = use_v[rr] ? 1 : 0;
    }
    __syncthreads();

    if (tid == 0) {
        int n0 = 0;
#pragma unroll
        for (int k = 0; k < 32; ++k) n0 += sh_use[k];
        int base0 = atomicAdd(&g_cnt[0], n0);
        int base1 = atomicAdd(&g_cnt[1], 32 - n0);
        int i0 = 0, i1 = 0;
#pragma unroll
        for (int k = 0; k < 32; ++k) {
            if (sh_use[k]) sh_slot[k] = base0 + (i0++);
            else           sh_slot[k] = BN2 - 1 - (base1 + (i1++));
        }
    }
    __syncthreads();

#pragma unroll
    for (int rr = 0; rr < 2; ++rr) {
        int b = b0 + rr;
        int slot = sh_slot[w*2+rr];
        if (lane == 0) {
            g_orig[slot] = b;
            g_posT[slot] = posb[rr] * INV_T;
        }

        float afq = (use_v[rr] ? inv_fv[rr] : inv_fi[rr]) * 127.f;
        float4 A4 = use_v[rr] ? Lfv[rr] : Lfi[rr];

        // A: row-major s8 by slot (coalesced 4B/lane)
        g_At8[slot * 32 + lane] = pack_s8(A4.x, A4.y, A4.z, A4.w, afq);

        // B fragment perm (m16n8k32 s8): one uint32 per lane per row
        int g  = b & 7;
        int nb = (w*2+rr) >> 3;            // 0..3 local nb block
        int kk = lane >> 3;                // 0..3
        int t4 = lane & 3;
        int reg = (lane >> 2) & 1;
        int idx = nb * 256 + kk * 64 + (g * 4 + t4) * 2 + reg;
        bvs[idx] = pack_s8(Lv[rr].x, Lv[rr].y, Lv[rr].z, Lv[rr].w,
                           inv_v[rr] * 127.f);
        bis[idx] = pack_s8(Li[rr].x, Li[rr].y, Li[rr].z, Li[rr].w,
                           inv_i[rr] * 127.f);
    }
    __syncthreads();

    // coalesced writeout: 4KB per matrix per block
    ((uint2*)(g_Bv8 + (size_t)blockIdx.x * 1024))[tid] = ((uint2*)bvs)[tid];
    ((uint2*)(g_Bi8 + (size_t)blockIdx.x * 1024))[tid] = ((uint2*)bis)[tid];
}

// ---------------------------------------------------------------------------
__global__ __launch_bounds__(256, 2) void gemm_lse_kernel() {
    extern __shared__ __align__(16) unsigned char sm[];
    __shared__ float red[128][4];

    const uint32_t smA  = s2u(sm);
    const uint32_t smB0 = smA + 16384u;
    const uint32_t smB1 = smA + 32768u;

    const int tid  = threadIdx.x;
    const int lane = tid & 31;
    const int wid  = tid >> 5;
    const int wm = wid >> 2;          // 0..1  (64-row block)
    const int wn = wid & 3;           // 0..3  (32-key block)

    const int c0 = g_cnt[0];
    const int bx = blockIdx.x, ks = blockIdx.y;
    const int grp = (bx > (c0 >> 7)) ? 1 : 0;
    const int row0 = bx << 7;
    const char* __restrict__ Kb = (const char*)(grp ? g_Bi8 : g_Bv8);

    if (bx == 0 && ks == 0 && tid == 0) g_c0s = c0;   // snapshot for finalize

    // prologue: A row-major s8 -> B1 staging (XOR-swizzled 16B chunks), B0
    {
        const char* Asrc = (const char*)g_At8 + (size_t)row0 * 128;
#pragma unroll
        for (int q = 0; q < 4; ++q) {
            int i = tid + q * 256;           // 0..1023 16B-chunks
            int row = i >> 3, c16 = i & 7;
            CPA16(smB1 + (uint32_t)(row * 128 + ((c16 ^ (row & 7)) * 16)),
                  Asrc + i * 16);
        }
        CP_COMMIT();
        const char* Bsrc = Kb + (size_t)ks * 16384;
#pragma unroll
        for (int q = 0; q < 4; ++q) {
            int i = (tid + q * 256) * 16;
            CPA16(smB0 + (uint32_t)i, Bsrc + i);
        }
        CP_COMMIT();
    }
    CP_WAIT1();                 // A staging resident (B0 may be pending)
    __syncthreads();

    // in-smem permute: staging (B1) -> fragment-order A (smA); conflict-free
    {
        int mb = wid;                      // 0..7
        int gq = lane >> 2, t4 = lane & 3;
        int r0 = mb * 16 + gq, r1 = r0 + 8;
        const uint32_t* st32 = (const uint32_t*)(sm + 32768);
#pragma unroll
        for (int kk = 0; kk < 4; ++kk) {
            int c16a = 2 * kk, c16b = 2 * kk + 1;
            uint4 o;
            o.x = st32[r0 * 32 + ((c16a ^ gq) << 2) + t4];
            o.y = st32[r1 * 32 + ((c16a ^ gq) << 2) + t4];
            o.z = st32[r0 * 32 + ((c16b ^ gq) << 2) + t4];
            o.w = st32[r1 * 32 + ((c16b ^ gq) << 2) + t4];
            ((uint4*)sm)[(mb * 4 + kk) * 32 + lane] = o;
        }
    }
    __syncthreads();

    float rsum[8];
#pragma unroll
    for (int i = 0; i < 8; ++i) rsum[i] = 0.f;

    const uint32_t aoff = smA + (uint32_t)(wm * 8192 + lane * 16);
    const uint32_t boff = (uint32_t)(wn * 4096 + lane * 8);

#pragma unroll 1
    for (int ci = 0; ci < NC; ++ci) {
        if (ci + 1 < NC) {
            const char* Bsrc = Kb + (size_t)(ks + (ci + 1) * KS) * 16384;
            uint32_t dst = ((ci + 1) & 1) ? smB1 : smB0;
#pragma unroll
            for (int q = 0; q < 4; ++q) {
                int i = (tid + q * 256) * 16;
                CPA16(dst + (uint32_t)i, Bsrc + i);
            }
            CP_COMMIT();
            CP_WAIT1();
        } else {
            CP_WAIT0();
        }
        __syncthreads();

        const uint32_t sB = ((ci & 1) ? smB1 : smB0) + boff;

        int c[4][4][4];
#pragma unroll
        for (int mi = 0; mi < 4; ++mi)
#pragma unroll
            for (int ni = 0; ni < 4; ++ni)
#pragma unroll
                for (int x = 0; x < 4; ++x) c[mi][ni][x] = 0;

#pragma unroll
        for (int kk = 0; kk < 4; ++kk) {
            uint32_t a[4][4], b[4][2];
#pragma unroll
            for (int mi = 0; mi < 4; ++mi)
                LDS128(a[mi], aoff + (uint32_t)(mi * 2048 + kk * 512));
#pragma unroll
            for (int ni = 0; ni < 4; ++ni)
                LDS64(b[ni], sB + (uint32_t)(ni * 1024 + kk * 256));
#pragma unroll
            for (int mi = 0; mi < 4; ++mi)
#pragma unroll
                for (int ni = 0; ni < 4; ++ni)
                    imma16832(c[mi][ni], a[mi], b[ni]);
        }

        // epilogue: s32 -> f32 via magic bias, scale+bias FFMA, ex2, add
#pragma unroll
        for (int mi = 0; mi < 4; ++mi) {
            float s0 = 0.f, s1 = 0.f;
#pragma unroll
            for (int ni = 0; ni < 4; ++ni) {
                float f0 = __int_as_float(c[mi][ni][0] + MAGIC_I);
                float f1 = __int_as_float(c[mi][ni][1] + MAGIC_I);
                float f2 = __int_as_float(c[mi][ni][2] + MAGIC_I);
                float f3 = __int_as_float(c[mi][ni][3] + MAGIC_I);
                s0 += ex2f(fmaf(f0, KQ, CEPI)) + ex2f(fmaf(f1, KQ, CEPI));
                s1 += ex2f(fmaf(f2, KQ, CEPI)) + ex2f(fmaf(f3, KQ, CEPI));
            }
            rsum[mi * 2]     += s0;
            rsum[mi * 2 + 1] += s1;
        }
        __syncthreads();
    }

    // reduce across the 4 col-lanes of each row
#pragma unroll
    for (int mi = 0; mi < 4; ++mi)
#pragma unroll
        for (int h = 0; h < 2; ++h) {
            float val = rsum[mi * 2 + h];
            val += __shfl_xor_sync(0xffffffffu, val, 1);
            val += __shfl_xor_sync(0xffffffffu, val, 2);
            if ((lane & 3) == 0)
                red[wm * 64 + mi * 16 + h * 8 + (lane >> 2)][wn] = val;
        }
    __syncthreads();

    if (tid < 128) {
        int slot = row0 + tid;
        float sum = red[tid][0] + red[tid][1] + red[tid][2] + red[tid][3];
        g_partial[ks * BN2 + slot] = sum;
    }
}

// ---------------------------------------------------------------------------
__global__ void finalize_kernel(float* __restrict__ out) {
    int s = blockIdx.x * 128 + threadIdx.x;      // 65*128 = 8320 exact
    int c0 = g_c0s;
    if (s < c0 || s >= c0 + 128) {               // skip the 128 pad slots
        float sum = g_partial[s] + g_partial[BN2 + s] +
                    g_partial[2 * BN2 + s] + g_partial[3 * BN2 + s];
        out[g_orig[s]] = fmaf(lg2f(sum), LN2, INV_T) - g_posT[s];
    }
    if (s == 0) { g_cnt[0] = 0; g_cnt[1] = 0; }  // reset for next replay
}

// ---------------------------------------------------------------------------
extern "C" void kernel_launch(void* const* d_in, const int* in_sizes, int n_in,
                              void* d_out, int out_size) {
    (void)in_sizes; (void)n_in; (void)out_size;
    const float* fv = (const float*)d_in[0];
    const float* fi = (const float*)d_in[1];
    const float* v  = (const float*)d_in[2];
    const float* vi = (const float*)d_in[3];
    float* out = (float*)d_out;

    cudaFuncSetAttribute(gemm_lse_kernel,
                         cudaFuncAttributeMaxDynamicSharedMemorySize, SMEM_TOT);

    prep_kernel<<<BN / 32, 512>>>(fv, fi, v, vi);
    gemm_lse_kernel<<<dim3(GRID_X, KS), 256, SMEM_TOT>>>();
    finalize_kernel<<<GRID_X, 128>>>(out);
}

// round 16
// speedup vs baseline: 2.6626x; 2.6626x over previous
#include <cuda_runtime.h>
#include <cuda_fp16.h>
#include <cstdint>

// ---------------------------------------------------------------------------
// PatchNCELoss B=8192 D=128 T=0.07 via mma.sync m16n8k16 fp16 (HMMA, f32 acc).
// loss[b] = 1/T + log(sum_k exp((S[b,k]-1)/T)) - pos[b]/T
// R16: 296 equal-work CTAs (exactly 2 per SM at occ 2) over global chunk
// ranges; per-row partials via atomicAdd into one g_partial[BN2] array
// (finalize re-zeroes for graph replays). GEMM core/prep = R14.
// ---------------------------------------------------------------------------

#define BN  8192
#define BN2 8320              // 65 * 128
#define DD  128
#define NJOBS 296             // 148 SMs x occ 2, pair sums 28..30 chunks
#define GRID_X 65

#define INV_T    14.285714285714286f
#define SCALE_L2 20.609929155556620f   /* log2(e)/T */
#define LN2      0.69314718055994531f

static __device__ __half g_At[BN2 * DD];   // row-major A*log2(e)/T (by slot)
static __device__ __half g_Bv[BN * DD];    // fragment-permuted v_n keys
static __device__ __half g_Bi[BN * DD];    // fragment-permuted i_n keys
static __device__ float  g_posT[BN2];
static __device__ int    g_orig[BN2];
static __device__ int    g_cnt[2];
static __device__ int    g_c0s;
static __device__ float  g_partial[BN2];   // zero-init; finalize re-zeroes

// smem: A 32KB | B0 32KB | B1 32KB (B1 doubles as A staging per segment)
#define SMEM_TOT 98304

// ---------------------------------------------------------------------------
__device__ __forceinline__ float ex2f(float x) {
    float r; asm("ex2.approx.f32 %0,%1;" : "=f"(r) : "f"(x)); return r;
}
__device__ __forceinline__ float lg2f(float x) {
    float r; asm("lg2.approx.f32 %0,%1;" : "=f"(r) : "f"(x)); return r;
}
__device__ __forceinline__ uint32_t s2u(const void* p) {
    uint32_t a;
    asm("{ .reg .u64 t; cvta.to.shared.u64 t, %1; cvt.u32.u64 %0, t; }"
        : "=r"(a) : "l"(p));
    return a;
}
#define CPA16(dst, src) \
    asm volatile("cp.async.cg.shared.global [%0], [%1], 16;" :: "r"(dst), "l"(src))
#define CP_COMMIT() asm volatile("cp.async.commit_group;" ::: "memory")
#define CP_WAIT1()  asm volatile("cp.async.wait_group 1;" ::: "memory")
#define CP_WAIT0()  asm volatile("cp.async.wait_group 0;" ::: "memory")

#define LDS128(r, a) \
    asm volatile("ld.shared.v4.b32 {%0,%1,%2,%3}, [%4];" \
        : "=r"((r)[0]), "=r"((r)[1]), "=r"((r)[2]), "=r"((r)[3]) : "r"(a))
#define LDS64(r, a) \
    asm volatile("ld.shared.v2.b32 {%0,%1}, [%2];" \
        : "=r"((r)[0]), "=r"((r)[1]) : "r"(a))

__device__ __forceinline__ void mma16816(float* c, const uint32_t* a,
                                         const uint32_t* b) {
    asm volatile(
        "mma.sync.aligned.m16n8k16.row.col.f32.f16.f16.f32 "
        "{%0,%1,%2,%3}, {%4,%5,%6,%7}, {%8,%9}, {%0,%1,%2,%3};"
        : "+f"(c[0]), "+f"(c[1]), "+f"(c[2]), "+f"(c[3])
        : "r"(a[0]), "r"(a[1]), "r"(a[2]), "r"(a[3]), "r"(b[0]), "r"(b[1]));
}

// ---------------------------------------------------------------------------
// prep: unchanged from R14 (MLP-8, aggregated atomics, coalesced perm writes)
__global__ __launch_bounds__(512) void prep_kernel(
        const float* __restrict__ fv, const float* __restrict__ fi,
        const float* __restrict__ v,  const float* __restrict__ vi) {
    __shared__ uint32_t bvs[2048];
    __shared__ uint32_t bis[2048];
    __shared__ int sh_use[32];
    __shared__ int sh_slot[32];

    int tid  = threadIdx.x;
    int w    = tid >> 5;
    int lane = tid & 31;
    int b0   = blockIdx.x * 32 + w * 2;

    float4 Lfv[2], Lfi[2], Lv[2], Li[2];
#pragma unroll
    for (int rr = 0; rr < 2; ++rr) {
        int b = b0 + rr;
        Lfv[rr] = __ldg((const float4*)(fv + b * DD + lane * 4));
        Lfi[rr] = __ldg((const float4*)(fi + b * DD + lane * 4));
        Lv[rr]  = __ldg((const float4*)(v  + b * DD + lane * 4));
        Li[rr]  = __ldg((const float4*)(vi + b * DD + lane * 4));
    }

    float s[12];
#pragma unroll
    for (int rr = 0; rr < 2; ++rr) {
        float4 a = Lfv[rr], c = Lfi[rr], d = Lv[rr], e = Li[rr];
        s[rr*6+0] = a.x*a.x + a.y*a.y + a.z*a.z + a.w*a.w;
        s[rr*6+1] = c.x*c.x + c.y*c.y + c.z*c.z + c.w*c.w;
        s[rr*6+2] = d.x*d.x + d.y*d.y + d.z*d.z + d.w*d.w;
        s[rr*6+3] = e.x*e.x + e.y*e.y + e.z*e.z + e.w*e.w;
        s[rr*6+4] = a.x*d.x + a.y*d.y + a.z*d.z + a.w*d.w;
        s[rr*6+5] = c.x*e.x + c.y*e.y + c.z*e.z + c.w*e.w;
    }
#pragma unroll
    for (int off = 16; off; off >>= 1)
#pragma unroll
        for (int k = 0; k < 12; ++k)
            s[k] += __shfl_xor_sync(0xffffffffu, s[k], off);

    float inv_fv[2], inv_fi[2], inv_v[2], inv_i[2], posb[2];
    bool use_v[2];
#pragma unroll
    for (int rr = 0; rr < 2; ++rr) {
        inv_fv[rr] = 1.f / fmaxf(sqrtf(s[rr*6+0]), 1e-12f);
        inv_fi[rr] = 1.f / fmaxf(sqrtf(s[rr*6+1]), 1e-12f);
        inv_v[rr]  = 1.f / fmaxf(sqrtf(s[rr*6+2]), 1e-12f);
        inv_i[rr]  = 1.f / fmaxf(sqrtf(s[rr*6+3]), 1e-12f);
        float pos_v = s[rr*6+4] * inv_fv[rr] * inv_v[rr];
        float pos_i = s[rr*6+5] * inv_fi[rr] * inv_i[rr];
        use_v[rr] = (pos_v >= pos_i);
        posb[rr] = use_v[rr] ? pos_v : pos_i;
        if (lane == 0) sh_use[w*2+rr] = use_v[rr] ? 1 : 0;
    }
    __syncthreads();

    if (tid == 0) {
        int n0 = 0;
#pragma unroll
        for (int k = 0; k < 32; ++k) n0 += sh_use[k];
        int base0 = atomicAdd(&g_cnt[0], n0);
        int base1 = atomicAdd(&g_cnt[1], 32 - n0);
        int i0 = 0, i1 = 0;
#pragma unroll
        for (int k = 0; k < 32; ++k) {
            if (sh_use[k]) sh_slot[k] = base0 + (i0++);
            else           sh_slot[k] = BN2 - 1 - (base1 + (i1++));
        }
    }
    __syncthreads();

#pragma unroll
    for (int rr = 0; rr < 2; ++rr) {
        int b = b0 + rr;
        int slot = sh_slot[w*2+rr];
        if (lane == 0) {
            g_orig[slot] = b;
            g_posT[slot] = posb[rr] * INV_T;
        }

        float af = (use_v[rr] ? inv_fv[rr] : inv_fi[rr]) * SCALE_L2;
        float4 A4 = use_v[rr] ? Lfv[rr] : Lfi[rr];
        float aval[4] = { A4.x, A4.y, A4.z, A4.w };
        float vval[4] = { Lv[rr].x * inv_v[rr], Lv[rr].y * inv_v[rr],
                          Lv[rr].z * inv_v[rr], Lv[rr].w * inv_v[rr] };
        float ival[4] = { Li[rr].x * inv_i[rr], Li[rr].y * inv_i[rr],
                          Li[rr].z * inv_i[rr], Li[rr].w * inv_i[rr] };

        {
            __half2 lo = __halves2half2(__float2half_rn(aval[0] * af),
                                        __float2half_rn(aval[1] * af));
            __half2 hi = __halves2half2(__float2half_rn(aval[2] * af),
                                        __float2half_rn(aval[3] * af));
            uint2 u;
            u.x = *reinterpret_cast<uint32_t*>(&lo);
            u.y = *reinterpret_cast<uint32_t*>(&hi);
            *reinterpret_cast<uint2*>(g_At + (size_t)slot * DD + lane * 4) = u;
        }

        int g  = b & 7;
        int nb = (w*2+rr) >> 3;
#pragma unroll
        for (int j = 0; j < 2; ++j) {
            int t0 = lane * 4 + j * 2;
            int kk = t0 >> 4, kh = (t0 >> 3) & 1, t4 = (t0 >> 1) & 3;
            int l2 = nb * 512 + (kk * 32 + g * 4 + t4) * 2 + kh;
            __half2 hv = __halves2half2(__float2half_rn(vval[j*2]),
                                        __float2half_rn(vval[j*2+1]));
            __half2 hb = __halves2half2(__float2half_rn(ival[j*2]),
                                        __float2half_rn(ival[j*2+1]));
            bvs[l2] = *reinterpret_cast<uint32_t*>(&hv);
            bis[l2] = *reinterpret_cast<uint32_t*>(&hb);
        }
    }
    __syncthreads();

    ((uint4*)(g_Bv + (size_t)blockIdx.x * 4096))[tid] = ((uint4*)bvs)[tid];
    ((uint4*)(g_Bi + (size_t)blockIdx.x * 4096))[tid] = ((uint4*)bis)[tid];
}

// ---------------------------------------------------------------------------
// gemm: 296 CTAs, each owns a contiguous global chunk range (chunk = 128 keys,
// global id = bx*64 + ch). Segments per row-tile: A load+permute prologue,
// double-buffered B loop, atomicAdd row partials.
__global__ __launch_bounds__(256, 2) void gemm_lse_kernel() {
    extern __shared__ __align__(16) unsigned char sm[];
    __shared__ float red[128][4];

    const uint32_t smA  = s2u(sm);
    const uint32_t smB0 = smA + 32768u;
    const uint32_t smB1 = smA + 65536u;

    const int tid  = threadIdx.x;
    const int lane = tid & 31;
    const int wid  = tid >> 5;
    const int wm = wid >> 2;
    const int wn = wid & 3;

    const int c0 = g_cnt[0];
    if (blockIdx.x == 0 && tid == 0) g_c0s = c0;
    const int t0 = c0 >> 7;

    const int j  = blockIdx.x;
    const int ex = (j < 16) ? j : 16;
    int g        = 14 * j + ex;                 // global chunk cursor
    const int ge = g + 14 + ((j < 16) ? 1 : 0);

    const uint32_t aoff = smA + (uint32_t)(wm * 16384 + lane * 16);
    const uint32_t boff = (uint32_t)(wn * 8192 + lane * 8);

    while (g < ge) {
        const int bx   = g >> 6;
        const int ch0  = g & 63;
        int segN = ((bx + 1) << 6) - g;
        if (g + segN > ge) segN = ge - g;
        const int grp  = (bx > t0) ? 1 : 0;
        const int row0 = bx << 7;
        const char* __restrict__ Kb = (const char*)(grp ? g_Bi : g_Bv);

        // ---- segment prologue: A -> staging (B1 region), B(ch0) -> B0
        {
            const char* Asrc = (const char*)g_At + (size_t)row0 * 256;
#pragma unroll
            for (int q = 0; q < 8; ++q) {
                int i = tid + q * 256;
                int row = i >> 4, c16 = i & 15;
                CPA16(smB1 + (uint32_t)(row * 256 + ((c16 ^ (row & 7)) * 16)),
                      Asrc + i * 16);
            }
            CP_COMMIT();
            const char* Bsrc = Kb + (size_t)ch0 * 32768;
#pragma unroll
            for (int q = 0; q < 8; ++q) {
                int i = (tid + q * 256) * 16;
                CPA16(smB0 + (uint32_t)i, Bsrc + i);
            }
            CP_COMMIT();
        }
        CP_WAIT1();
        __syncthreads();

        // in-smem permute: staging -> fragment-order A (conflict-free)
        {
            int gq = lane >> 2, t4 = lane & 3;
            const uint32_t* st32 = (const uint32_t*)(sm + 65536);
#pragma unroll
            for (int mb = 0; mb < 8; ++mb) {
                int rA = mb * 16 + gq, rB = rA + 8;
                int e0 = (((2 * wid)     ^ gq) * 4) + t4;
                int e1 = (((2 * wid + 1) ^ gq) * 4) + t4;
                uint4 o;
                o.x = st32[rA * 64 + e0];
                o.y = st32[rB * 64 + e0];
                o.z = st32[rA * 64 + e1];
                o.w = st32[rB * 64 + e1];
                ((uint4*)sm)[(mb * 8 + wid) * 32 + lane] = o;
            }
        }
        __syncthreads();

        float rsum[8];
#pragma unroll
        for (int i = 0; i < 8; ++i) rsum[i] = 0.f;

#pragma unroll 1
        for (int ci = 0; ci < segN; ++ci) {
            if (ci + 1 < segN) {
                const char* Bs = Kb + (size_t)(ch0 + ci + 1) * 32768;
                uint32_t dst = ((ci + 1) & 1) ? smB1 : smB0;
#pragma unroll
                for (int q = 0; q < 8; ++q) {
                    int i = (tid + q * 256) * 16;
                    CPA16(dst + (uint32_t)i, Bs + i);
                }
                CP_COMMIT();
                CP_WAIT1();
            } else {
                CP_WAIT0();
            }
            __syncthreads();

            const uint32_t sB = ((ci & 1) ? smB1 : smB0) + boff;

            float c[4][4][4];
#pragma unroll
            for (int mi = 0; mi < 4; ++mi)
#pragma unroll
                for (int ni = 0; ni < 4; ++ni)
#pragma unroll
                    for (int x = 0; x < 4; ++x) c[mi][ni][x] = -SCALE_L2;

#pragma unroll
            for (int kk = 0; kk < 8; ++kk) {
                uint32_t a[4][4], b[4][2];
#pragma unroll
                for (int mi = 0; mi < 4; ++mi)
                    LDS128(a[mi], aoff + (uint32_t)(mi * 4096 + kk * 512));
#pragma unroll
                for (int ni = 0; ni < 4; ++ni)
                    LDS64(b[ni], sB + (uint32_t)(ni * 2048 + kk * 256));
#pragma unroll
                for (int mi = 0; mi < 4; ++mi)
#pragma unroll
                    for (int ni = 0; ni < 4; ++ni)
                        mma16816(c[mi][ni], a[mi], b[ni]);
            }

#pragma unroll
            for (int mi = 0; mi < 4; ++mi) {
                float s0 = 0.f, s1 = 0.f;
#pragma unroll
                for (int ni = 0; ni < 4; ++ni) {
                    s0 += ex2f(c[mi][ni][0]) + ex2f(c[mi][ni][1]);
                    s1 += ex2f(c[mi][ni][2]) + ex2f(c[mi][ni][3]);
                }
                rsum[mi * 2]     += s0;
                rsum[mi * 2 + 1] += s1;
            }
            __syncthreads();
        }

        // ---- segment flush: reduce 4 col-lanes, atomicAdd row partials
#pragma unroll
        for (int mi = 0; mi < 4; ++mi)
#pragma unroll
            for (int h = 0; h < 2; ++h) {
                float val = rsum[mi * 2 + h];
                val += __shfl_xor_sync(0xffffffffu, val, 1);
                val += __shfl_xor_sync(0xffffffffu, val, 2);
                if ((lane & 3) == 0)
                    red[wm * 64 + mi * 16 + h * 8 + (lane >> 2)][wn] = val;
            }
        __syncthreads();
        if (tid < 128) {
            float sum = red[tid][0] + red[tid][1] + red[tid][2] + red[tid][3];
            atomicAdd(&g_partial[row0 + tid], sum);
        }
        __syncthreads();

        g += segN;
    }
}

// ---------------------------------------------------------------------------
__global__ void finalize_kernel(float* __restrict__ out) {
    int s = blockIdx.x * 128 + threadIdx.x;      // 65*128 = 8320 exact
    int c0 = g_c0s;
    float sum = g_partial[s];
    if (s < c0 || s >= c0 + 128)                 // skip the 128 pad slots
        out[g_orig[s]] = fmaf(lg2f(sum), LN2, INV_T) - g_posT[s];
    g_partial[s] = 0.f;                          // re-zero for next replay
    if (s == 0) { g_cnt[0] = 0; g_cnt[1] = 0; }
}

// ---------------------------------------------------------------------------
extern "C" void kernel_launch(void* const* d_in, const int* in_sizes, int n_in,
                              void* d_out, int out_size) {
    (void)in_sizes; (void)n_in; (void)out_size;
    const float* fv = (const float*)d_in[0];
    const float* fi = (const float*)d_in[1];
    const float* v  = (const float*)d_in[2];
    const float* vi = (const float*)d_in[3];
    float* out = (float*)d_out;

    cudaFuncSetAttribute(gemm_lse_kernel,
                         cudaFuncAttributeMaxDynamicSharedMemorySize, SMEM_TOT);

    prep_kernel<<<BN / 32, 512>>>(fv, fi, v, vi);
    gemm_lse_kernel<<<NJOBS, 256, SMEM_TOT>>>();
    finalize_kernel<<<GRID_X, 128>>>(out);
}